// round 1
// baseline (speedup 1.0000x reference)
#include <cuda_runtime.h>
#include <cstdint>
#include <cstddef>

#define N_NODES 50000
#define N_EDGES 800000
#define IN_DIM 64
#define OUT_DIM 64
#define EDGE_DIM 16

// Scratch (device globals: no allocation allowed)
__device__ float g_xw1[N_NODES * OUT_DIM];   // x @ W1[:64,:] + b1, per node
__device__ float g_agg[N_NODES * OUT_DIM];   // scatter-add accumulator
__device__ float g_cnt[N_NODES];             // in-degree counts

__device__ __forceinline__ void red_add_v4(float* addr, float4 v) {
    asm volatile("red.global.add.v4.f32 [%0], {%1, %2, %3, %4};"
                 :: "l"(addr), "f"(v.x), "f"(v.y), "f"(v.z), "f"(v.w)
                 : "memory");
}

// ---------------------------------------------------------------------------
// Zero the scatter buffers
// ---------------------------------------------------------------------------
__global__ void zero_kernel() {
    int i = blockIdx.x * blockDim.x + threadIdx.x;
    int stride = gridDim.x * blockDim.x;
    float4 z = make_float4(0.f, 0.f, 0.f, 0.f);
    float4* a4 = reinterpret_cast<float4*>(g_agg);
    const int n4 = N_NODES * OUT_DIM / 4;
    for (int j = i; j < n4; j += stride) a4[j] = z;
    for (int j = i; j < N_NODES; j += stride) g_cnt[j] = 0.0f;
}

// ---------------------------------------------------------------------------
// Per-node precompute: g_xw1[n] = x[n] @ W1[0:64,:] + b1   (warp per node)
// ---------------------------------------------------------------------------
__global__ void __launch_bounds__(256) precompute_kernel(
        const float* __restrict__ x,
        const float* __restrict__ W1,
        const float* __restrict__ b1) {
    __shared__ float2 sW[64 * 32];   // sW[k*32+l] = (W1[k][l], W1[k][l+32])
    int tid = threadIdx.x;
    for (int idx = tid; idx < 64 * 32; idx += 256) {
        int k = idx >> 5, l = idx & 31;
        sW[idx] = make_float2(W1[k * 64 + l], W1[k * 64 + l + 32]);
    }
    __syncthreads();

    int warp = tid >> 5, lane = tid & 31;
    int n = blockIdx.x * 8 + warp;
    if (n >= N_NODES) return;

    const float* xr = x + (size_t)n * 64;
    float x0 = xr[lane], x1 = xr[lane + 32];
    float acc0 = b1[lane], acc1 = b1[lane + 32];

    #pragma unroll
    for (int i = 0; i < 32; i++) {
        float v = __shfl_sync(0xffffffffu, x0, i);
        float2 w = sW[i * 32 + lane];
        acc0 = fmaf(v, w.x, acc0);
        acc1 = fmaf(v, w.y, acc1);
    }
    #pragma unroll
    for (int i = 0; i < 32; i++) {
        float v = __shfl_sync(0xffffffffu, x1, i);
        float2 w = sW[(32 + i) * 32 + lane];
        acc0 = fmaf(v, w.x, acc0);
        acc1 = fmaf(v, w.y, acc1);
    }
    g_xw1[(size_t)n * 64 + lane]      = acc0;
    g_xw1[(size_t)n * 64 + lane + 32] = acc1;
}

// ---------------------------------------------------------------------------
// Edge kernel: lane-per-edge.
//   t = relu(g_xw1[src] + ef @ W1[64:80,:])      (layer1, b1 already folded)
//   m = t @ W2 + b2                              (layer2)
//   red.add m -> g_agg[dst], red.add 1 -> g_cnt[dst]
// Weights broadcast from shared as float4 (conflict-free broadcast LDS.128).
// ---------------------------------------------------------------------------
__global__ void __launch_bounds__(256) edge_kernel(
        const int*   __restrict__ ei,
        const float* __restrict__ ef,
        const float* __restrict__ W1,
        const float* __restrict__ W2,
        const float* __restrict__ b2) {
    __shared__ float4 sW1e[16 * 16];  // [i][j4] of W1 rows 64..79
    __shared__ float4 sW2[64 * 16];   // [i][j4]
    __shared__ float4 sb2[16];

    int tid = threadIdx.x;
    for (int idx = tid; idx < 16 * 16; idx += 256) {
        int i = idx >> 4, j = idx & 15;
        const float* r = W1 + (size_t)(64 + i) * 64 + j * 4;
        sW1e[idx] = make_float4(r[0], r[1], r[2], r[3]);
    }
    for (int idx = tid; idx < 64 * 16; idx += 256) {
        int i = idx >> 4, j = idx & 15;
        const float* r = W2 + (size_t)i * 64 + j * 4;
        sW2[idx] = make_float4(r[0], r[1], r[2], r[3]);
    }
    if (tid < 16) {
        const float* r = b2 + tid * 4;
        sb2[tid] = make_float4(r[0], r[1], r[2], r[3]);
    }
    __syncthreads();

    int e = blockIdx.x * 256 + tid;
    if (e >= N_EDGES) return;

    int s = ei[e];
    int d = ei[N_EDGES + e];

    // t <- xw1[src]   (gather, L2-resident)
    float t[64];
    const float4* xr = reinterpret_cast<const float4*>(g_xw1 + (size_t)s * 64);
    #pragma unroll
    for (int j = 0; j < 16; j++) {
        float4 v = xr[j];
        t[4*j] = v.x; t[4*j+1] = v.y; t[4*j+2] = v.z; t[4*j+3] = v.w;
    }

    // edge features
    float efr[16];
    const float4* er = reinterpret_cast<const float4*>(ef + (size_t)e * 16);
    #pragma unroll
    for (int j = 0; j < 4; j++) {
        float4 v = er[j];
        efr[4*j] = v.x; efr[4*j+1] = v.y; efr[4*j+2] = v.z; efr[4*j+3] = v.w;
    }

    // layer 1: t += ef @ W1e
    #pragma unroll
    for (int i = 0; i < 16; i++) {
        float ev = efr[i];
        #pragma unroll
        for (int j = 0; j < 16; j++) {
            float4 w = sW1e[i * 16 + j];
            t[4*j]   = fmaf(ev, w.x, t[4*j]);
            t[4*j+1] = fmaf(ev, w.y, t[4*j+1]);
            t[4*j+2] = fmaf(ev, w.z, t[4*j+2]);
            t[4*j+3] = fmaf(ev, w.w, t[4*j+3]);
        }
    }
    #pragma unroll
    for (int j = 0; j < 64; j++) t[j] = fmaxf(t[j], 0.0f);

    // layer 2 in 4 output chunks of 16 (rolled c-loop keeps I$ footprint sane)
    float* aggbase = g_agg + (size_t)d * 64;
    #pragma unroll 1
    for (int c = 0; c < 4; c++) {
        float4 m0 = sb2[c*4+0], m1 = sb2[c*4+1], m2 = sb2[c*4+2], m3 = sb2[c*4+3];
        #pragma unroll
        for (int i = 0; i < 64; i++) {
            float ti = t[i];
            float4 w0 = sW2[i*16 + c*4 + 0];
            float4 w1 = sW2[i*16 + c*4 + 1];
            float4 w2 = sW2[i*16 + c*4 + 2];
            float4 w3 = sW2[i*16 + c*4 + 3];
            m0.x = fmaf(ti, w0.x, m0.x); m0.y = fmaf(ti, w0.y, m0.y);
            m0.z = fmaf(ti, w0.z, m0.z); m0.w = fmaf(ti, w0.w, m0.w);
            m1.x = fmaf(ti, w1.x, m1.x); m1.y = fmaf(ti, w1.y, m1.y);
            m1.z = fmaf(ti, w1.z, m1.z); m1.w = fmaf(ti, w1.w, m1.w);
            m2.x = fmaf(ti, w2.x, m2.x); m2.y = fmaf(ti, w2.y, m2.y);
            m2.z = fmaf(ti, w2.z, m2.z); m2.w = fmaf(ti, w2.w, m2.w);
            m3.x = fmaf(ti, w3.x, m3.x); m3.y = fmaf(ti, w3.y, m3.y);
            m3.z = fmaf(ti, w3.z, m3.z); m3.w = fmaf(ti, w3.w, m3.w);
        }
        red_add_v4(aggbase + c*16 + 0,  m0);
        red_add_v4(aggbase + c*16 + 4,  m1);
        red_add_v4(aggbase + c*16 + 8,  m2);
        red_add_v4(aggbase + c*16 + 12, m3);
    }
    atomicAdd(&g_cnt[d], 1.0f);
}

// ---------------------------------------------------------------------------
// Node kernel: mean-aggregate, update MLP + relu + residual + LayerNorm.
// Warp per node; W3 packed float2 in shared; shuffle-broadcast inputs.
// ---------------------------------------------------------------------------
__global__ void __launch_bounds__(256) node_kernel(
        const float* __restrict__ x,
        const float* __restrict__ W3,
        const float* __restrict__ b3,
        const float* __restrict__ gamma,
        const float* __restrict__ beta,
        float* __restrict__ out) {
    __shared__ float2 sW[128 * 32];   // sW[k*32+l] = (W3[k][l], W3[k][l+32])
    int tid = threadIdx.x;
    for (int idx = tid; idx < 128 * 32; idx += 256) {
        int k = idx >> 5, l = idx & 31;
        sW[idx] = make_float2(W3[k * 64 + l], W3[k * 64 + l + 32]);
    }
    __syncthreads();

    int warp = tid >> 5, lane = tid & 31;
    int n = blockIdx.x * 8 + warp;
    if (n >= N_NODES) return;

    const float* xr = x + (size_t)n * 64;
    float x0 = xr[lane], x1 = xr[lane + 32];
    float a0 = g_agg[(size_t)n * 64 + lane];
    float a1 = g_agg[(size_t)n * 64 + lane + 32];
    float inv = 1.0f / (g_cnt[n] + 1e-8f);
    a0 *= inv; a1 *= inv;

    float acc0 = b3[lane], acc1 = b3[lane + 32];
    #pragma unroll
    for (int i = 0; i < 32; i++) {
        float v = __shfl_sync(0xffffffffu, x0, i);
        float2 w = sW[i * 32 + lane];
        acc0 = fmaf(v, w.x, acc0); acc1 = fmaf(v, w.y, acc1);
    }
    #pragma unroll
    for (int i = 0; i < 32; i++) {
        float v = __shfl_sync(0xffffffffu, x1, i);
        float2 w = sW[(32 + i) * 32 + lane];
        acc0 = fmaf(v, w.x, acc0); acc1 = fmaf(v, w.y, acc1);
    }
    #pragma unroll
    for (int i = 0; i < 32; i++) {
        float v = __shfl_sync(0xffffffffu, a0, i);
        float2 w = sW[(64 + i) * 32 + lane];
        acc0 = fmaf(v, w.x, acc0); acc1 = fmaf(v, w.y, acc1);
    }
    #pragma unroll
    for (int i = 0; i < 32; i++) {
        float v = __shfl_sync(0xffffffffu, a1, i);
        float2 w = sW[(96 + i) * 32 + lane];
        acc0 = fmaf(v, w.x, acc0); acc1 = fmaf(v, w.y, acc1);
    }

    float u0 = fmaxf(acc0, 0.0f) + x0;
    float u1 = fmaxf(acc1, 0.0f) + x1;

    float s  = u0 + u1;
    float ss = fmaf(u0, u0, u1 * u1);
    #pragma unroll
    for (int o = 16; o > 0; o >>= 1) {
        s  += __shfl_xor_sync(0xffffffffu, s, o);
        ss += __shfl_xor_sync(0xffffffffu, ss, o);
    }
    float mu  = s * (1.0f / 64.0f);
    float var = ss * (1.0f / 64.0f) - mu * mu;
    float r   = rsqrtf(var + 1e-5f);

    out[(size_t)n * 64 + lane]      = (u0 - mu) * r * gamma[lane]      + beta[lane];
    out[(size_t)n * 64 + lane + 32] = (u1 - mu) * r * gamma[lane + 32] + beta[lane + 32];
}

// ---------------------------------------------------------------------------
extern "C" void kernel_launch(void* const* d_in, const int* in_sizes, int n_in,
                              void* d_out, int out_size) {
    const float* x     = (const float*)d_in[0];
    const int*   ei    = (const int*)  d_in[1];
    const float* ef    = (const float*)d_in[2];
    const float* W1    = (const float*)d_in[3];
    const float* b1    = (const float*)d_in[4];
    const float* W2    = (const float*)d_in[5];
    const float* b2    = (const float*)d_in[6];
    const float* W3    = (const float*)d_in[7];
    const float* b3    = (const float*)d_in[8];
    const float* gamma = (const float*)d_in[9];
    const float* beta  = (const float*)d_in[10];
    float* out = (float*)d_out;

    (void)in_sizes; (void)n_in; (void)out_size;

    zero_kernel<<<1024, 256>>>();
    precompute_kernel<<<(N_NODES + 7) / 8, 256>>>(x, W1, b1);
    edge_kernel<<<(N_EDGES + 255) / 256, 256>>>(ei, ef, W1, W2, b2);
    node_kernel<<<(N_NODES + 7) / 8, 256>>>(x, W3, b3, gamma, beta, out);
}

// round 2
// speedup vs baseline: 1.1431x; 1.1431x over previous
#include <cuda_runtime.h>
#include <cstdint>
#include <cstddef>

#define N_NODES 50000
#define N_EDGES 800000

// Scratch (device globals: no allocation allowed)
__device__ __align__(16) float g_xw1[N_NODES * 64];   // x @ W1[:64,:] + b1
__device__ __align__(16) float g_agg[N_NODES * 64];   // scatter-add accumulator
__device__ float g_cnt[N_NODES];                      // in-degree counts

typedef unsigned long long u64;

// ---- packed f32x2 helpers (SASS FFMA2 — only reachable via PTX) -----------
__device__ __forceinline__ u64 pack2(float v) {
    u64 r; asm("mov.b64 %0, {%1, %1};" : "=l"(r) : "f"(v)); return r;
}
__device__ __forceinline__ void unpack2(u64 v, float &lo, float &hi) {
    asm("mov.b64 {%0, %1}, %2;" : "=f"(lo), "=f"(hi) : "l"(v));
}
__device__ __forceinline__ void ffma2(u64 &d, u64 a, u64 b) {
    asm("fma.rn.f32x2 %0, %1, %2, %0;" : "+l"(d) : "l"(a), "l"(b));
}
__device__ __forceinline__ void red_add_v4(float* addr, float4 v) {
    asm volatile("red.global.add.v4.f32 [%0], {%1, %2, %3, %4};"
                 :: "l"(addr), "f"(v.x), "f"(v.y), "f"(v.z), "f"(v.w)
                 : "memory");
}

// ---------------------------------------------------------------------------
// Zero the scatter buffers
// ---------------------------------------------------------------------------
__global__ void zero_kernel() {
    int i = blockIdx.x * blockDim.x + threadIdx.x;
    int stride = gridDim.x * blockDim.x;
    float4 z = make_float4(0.f, 0.f, 0.f, 0.f);
    float4* a4 = reinterpret_cast<float4*>(g_agg);
    const int n4 = N_NODES * 64 / 4;
    for (int j = i; j < n4; j += stride) a4[j] = z;
    for (int j = i; j < N_NODES; j += stride) g_cnt[j] = 0.0f;
}

// ---------------------------------------------------------------------------
// Per-node precompute: g_xw1[n] = x[n] @ W1[0:64,:] + b1
// Thread per node, weights broadcast from shared as ulonglong2, FFMA2 math.
// ---------------------------------------------------------------------------
__global__ void __launch_bounds__(128) precompute_kernel(
        const float* __restrict__ x,
        const float* __restrict__ W1,
        const float* __restrict__ b1) {
    __shared__ ulonglong2 sW[64 * 16];   // row k: 16 x (4 packed floats)
    __shared__ ulonglong2 sb[16];
    int tid = threadIdx.x;
    const ulonglong2* W1v = reinterpret_cast<const ulonglong2*>(W1);
    for (int idx = tid; idx < 64 * 16; idx += 128) sW[idx] = W1v[idx];
    if (tid < 16) sb[tid] = reinterpret_cast<const ulonglong2*>(b1)[tid];
    __syncthreads();

    int n = blockIdx.x * 128 + tid;
    if (n >= N_NODES) return;

    u64 acc[32];
    #pragma unroll
    for (int j = 0; j < 16; j++) { ulonglong2 v = sb[j]; acc[2*j] = v.x; acc[2*j+1] = v.y; }

    const float4* xr = reinterpret_cast<const float4*>(x + (size_t)n * 64);
    #pragma unroll 1
    for (int c = 0; c < 2; c++) {
        float v[32];
        #pragma unroll
        for (int j = 0; j < 8; j++) {
            float4 f = xr[c * 8 + j];
            v[4*j] = f.x; v[4*j+1] = f.y; v[4*j+2] = f.z; v[4*j+3] = f.w;
        }
        #pragma unroll
        for (int i = 0; i < 32; i++) {
            u64 a = pack2(v[i]);
            #pragma unroll
            for (int j = 0; j < 16; j++) {
                ulonglong2 w = sW[(c * 32 + i) * 16 + j];
                ffma2(acc[2*j], a, w.x);
                ffma2(acc[2*j+1], a, w.y);
            }
        }
    }
    ulonglong2* o = reinterpret_cast<ulonglong2*>(g_xw1 + (size_t)n * 64);
    #pragma unroll
    for (int j = 0; j < 16; j++) {
        ulonglong2 v; v.x = acc[2*j]; v.y = acc[2*j+1]; o[j] = v;
    }
}

// ---------------------------------------------------------------------------
// Edge kernel: lane-per-edge, FFMA2 throughout.
//   t = relu(g_xw1[src] + ef @ W1[64:80,:])
//   m = t @ W2 + b2 ;  red.add m -> g_agg[dst] ; red.add 1 -> g_cnt[dst]
// ---------------------------------------------------------------------------
__global__ void __launch_bounds__(128) edge_kernel(
        const int*   __restrict__ ei,
        const float* __restrict__ ef,
        const float* __restrict__ W1,
        const float* __restrict__ W2,
        const float* __restrict__ b2) {
    __shared__ ulonglong2 sW1e[16 * 16];  // W1 rows 64..79
    __shared__ ulonglong2 sW2[64 * 16];
    __shared__ ulonglong2 sb2[16];

    int tid = threadIdx.x;
    const ulonglong2* W1v = reinterpret_cast<const ulonglong2*>(W1);
    const ulonglong2* W2v = reinterpret_cast<const ulonglong2*>(W2);
    for (int idx = tid; idx < 16 * 16; idx += 128) sW1e[idx] = W1v[1024 + idx];
    for (int idx = tid; idx < 64 * 16; idx += 128) sW2[idx] = W2v[idx];
    if (tid < 16) sb2[tid] = reinterpret_cast<const ulonglong2*>(b2)[tid];
    __syncthreads();

    int e = blockIdx.x * 128 + tid;   // N_EDGES % 128 == 0
    int s = ei[e];
    int d = ei[N_EDGES + e];

    // layer-1 accumulator <- xw1[src]  (L2-resident gather, already pair-packed)
    u64 acc[32];
    const ulonglong2* xr = reinterpret_cast<const ulonglong2*>(g_xw1 + (size_t)s * 64);
    #pragma unroll
    for (int j = 0; j < 16; j++) { ulonglong2 v = xr[j]; acc[2*j] = v.x; acc[2*j+1] = v.y; }

    float efr[16];
    const float4* er = reinterpret_cast<const float4*>(ef + (size_t)e * 16);
    #pragma unroll
    for (int j = 0; j < 4; j++) {
        float4 f = er[j];
        efr[4*j] = f.x; efr[4*j+1] = f.y; efr[4*j+2] = f.z; efr[4*j+3] = f.w;
    }

    // layer 1: acc += ef @ W1e
    #pragma unroll
    for (int i = 0; i < 16; i++) {
        u64 a = pack2(efr[i]);
        #pragma unroll
        for (int j = 0; j < 16; j++) {
            ulonglong2 w = sW1e[i * 16 + j];
            ffma2(acc[2*j], a, w.x);
            ffma2(acc[2*j+1], a, w.y);
        }
    }

    // relu -> scalar t
    float t[64];
    #pragma unroll
    for (int j = 0; j < 32; j++) {
        float lo, hi; unpack2(acc[j], lo, hi);
        t[2*j] = fmaxf(lo, 0.0f); t[2*j+1] = fmaxf(hi, 0.0f);
    }

    // layer 2 in 4 output chunks of 16 (unroll-1 keeps I$ footprint sane)
    float* aggbase = g_agg + (size_t)d * 64;
    #pragma unroll 1
    for (int c = 0; c < 4; c++) {
        u64 m[8];
        #pragma unroll
        for (int j = 0; j < 4; j++) { ulonglong2 v = sb2[c*4 + j]; m[2*j] = v.x; m[2*j+1] = v.y; }
        #pragma unroll
        for (int i = 0; i < 64; i++) {
            u64 a = pack2(t[i]);
            #pragma unroll
            for (int j = 0; j < 4; j++) {
                ulonglong2 w = sW2[i * 16 + c * 4 + j];
                ffma2(m[2*j], a, w.x);
                ffma2(m[2*j+1], a, w.y);
            }
        }
        #pragma unroll
        for (int j = 0; j < 4; j++) {
            float4 v;
            unpack2(m[2*j],   v.x, v.y);
            unpack2(m[2*j+1], v.z, v.w);
            red_add_v4(aggbase + c * 16 + 4 * j, v);
        }
    }
    atomicAdd(&g_cnt[d], 1.0f);
}

// ---------------------------------------------------------------------------
// Node kernel: thread per node. mean-agg, update MLP (FFMA2) + relu +
// residual + LayerNorm entirely in registers (no shuffles).
// ---------------------------------------------------------------------------
__global__ void __launch_bounds__(128) node_kernel(
        const float* __restrict__ x,
        const float* __restrict__ W3,
        const float* __restrict__ b3,
        const float* __restrict__ gamma,
        const float* __restrict__ beta,
        float* __restrict__ out) {
    __shared__ ulonglong2 sW[128 * 16];  // 32 KB
    __shared__ ulonglong2 sb[16];
    int tid = threadIdx.x;
    const ulonglong2* W3v = reinterpret_cast<const ulonglong2*>(W3);
    for (int idx = tid; idx < 128 * 16; idx += 128) sW[idx] = W3v[idx];
    if (tid < 16) sb[tid] = reinterpret_cast<const ulonglong2*>(b3)[tid];
    __syncthreads();

    int n = blockIdx.x * 128 + tid;
    if (n >= N_NODES) return;

    float inv = 1.0f / (g_cnt[n] + 1e-8f);

    u64 acc[32];
    #pragma unroll
    for (int j = 0; j < 16; j++) { ulonglong2 v = sb[j]; acc[2*j] = v.x; acc[2*j+1] = v.y; }

    const float4* xr = reinterpret_cast<const float4*>(x + (size_t)n * 64);
    const float4* ar = reinterpret_cast<const float4*>(g_agg + (size_t)n * 64);

    #pragma unroll 1
    for (int c = 0; c < 4; c++) {
        float v[32];
        bool isx = (c < 2);
        const float4* p = isx ? (xr + (c & 1) * 8) : (ar + (c & 1) * 8);
        #pragma unroll
        for (int j = 0; j < 8; j++) {
            float4 f = p[j];
            v[4*j] = f.x; v[4*j+1] = f.y; v[4*j+2] = f.z; v[4*j+3] = f.w;
        }
        if (!isx) {
            #pragma unroll
            for (int j = 0; j < 32; j++) v[j] *= inv;
        }
        #pragma unroll
        for (int i = 0; i < 32; i++) {
            u64 a = pack2(v[i]);
            #pragma unroll
            for (int j = 0; j < 16; j++) {
                ulonglong2 w = sW[(c * 32 + i) * 16 + j];
                ffma2(acc[2*j], a, w.x);
                ffma2(acc[2*j+1], a, w.y);
            }
        }
    }

    // relu + residual
    float u[64];
    #pragma unroll
    for (int j = 0; j < 16; j++) {
        float4 f = xr[j];
        float a0, a1, a2, a3;
        unpack2(acc[2*j],   a0, a1);
        unpack2(acc[2*j+1], a2, a3);
        u[4*j]   = fmaxf(a0, 0.0f) + f.x;
        u[4*j+1] = fmaxf(a1, 0.0f) + f.y;
        u[4*j+2] = fmaxf(a2, 0.0f) + f.z;
        u[4*j+3] = fmaxf(a3, 0.0f) + f.w;
    }

    // LayerNorm (per-thread, no cross-lane traffic)
    float s = 0.0f, ss = 0.0f;
    #pragma unroll
    for (int j = 0; j < 64; j++) { s += u[j]; ss = fmaf(u[j], u[j], ss); }
    float mu  = s * (1.0f / 64.0f);
    float var = ss * (1.0f / 64.0f) - mu * mu;
    float r   = rsqrtf(var + 1e-5f);

    const float4* gv = reinterpret_cast<const float4*>(gamma);
    const float4* bv = reinterpret_cast<const float4*>(beta);
    float4* o = reinterpret_cast<float4*>(out + (size_t)n * 64);
    #pragma unroll
    for (int j = 0; j < 16; j++) {
        float4 g = gv[j], bb = bv[j], v;
        v.x = (u[4*j]   - mu) * r * g.x + bb.x;
        v.y = (u[4*j+1] - mu) * r * g.y + bb.y;
        v.z = (u[4*j+2] - mu) * r * g.z + bb.z;
        v.w = (u[4*j+3] - mu) * r * g.w + bb.w;
        o[j] = v;
    }
}

// ---------------------------------------------------------------------------
extern "C" void kernel_launch(void* const* d_in, const int* in_sizes, int n_in,
                              void* d_out, int out_size) {
    const float* x     = (const float*)d_in[0];
    const int*   ei    = (const int*)  d_in[1];
    const float* ef    = (const float*)d_in[2];
    const float* W1    = (const float*)d_in[3];
    const float* b1    = (const float*)d_in[4];
    const float* W2    = (const float*)d_in[5];
    const float* b2    = (const float*)d_in[6];
    const float* W3    = (const float*)d_in[7];
    const float* b3    = (const float*)d_in[8];
    const float* gamma = (const float*)d_in[9];
    const float* beta  = (const float*)d_in[10];
    float* out = (float*)d_out;

    (void)in_sizes; (void)n_in; (void)out_size;

    zero_kernel<<<1024, 256>>>();
    precompute_kernel<<<(N_NODES + 127) / 128, 128>>>(x, W1, b1);
    edge_kernel<<<N_EDGES / 128, 128>>>(ei, ef, W1, W2, b2);
    node_kernel<<<(N_NODES + 127) / 128, 128>>>(x, W3, b3, gamma, beta, out);
}

// round 3
// speedup vs baseline: 1.9151x; 1.6753x over previous
#include <cuda_runtime.h>
#include <cstdint>
#include <cstddef>

#define N_NODES 50000
#define N_EDGES 800000

// Scratch (device globals: no allocation allowed)
__device__ __align__(16) float g_xw1[N_NODES * 64];   // x@W1[:64]+b1, then reused for agg@W2 result
__device__ __align__(16) float g_agg[N_NODES * 64];   // scatter-add of relu(h)
__device__ float g_cnt[N_NODES];                      // in-degree counts

typedef unsigned long long u64;

__device__ __forceinline__ u64 pack2(float v) {
    u64 r; asm("mov.b64 %0, {%1, %1};" : "=l"(r) : "f"(v)); return r;
}
__device__ __forceinline__ void unpack2(u64 v, float &lo, float &hi) {
    asm("mov.b64 {%0, %1}, %2;" : "=f"(lo), "=f"(hi) : "l"(v));
}
__device__ __forceinline__ void ffma2(u64 &d, u64 a, u64 b) {
    asm("fma.rn.f32x2 %0, %1, %2, %0;" : "+l"(d) : "l"(a), "l"(b));
}
__device__ __forceinline__ void red_add_v4(float* addr, float4 v) {
    asm volatile("red.global.add.v4.f32 [%0], {%1, %2, %3, %4};"
                 :: "l"(addr), "f"(v.x), "f"(v.y), "f"(v.z), "f"(v.w)
                 : "memory");
}

// ---------------------------------------------------------------------------
// Precompute: g_xw1[n] = x[n] @ W1[0:64,:] + b1, and zero g_agg row / g_cnt.
// Thread per node; weights broadcast from shared; FFMA2 math.
// ---------------------------------------------------------------------------
__global__ void __launch_bounds__(128) precompute_kernel(
        const float* __restrict__ x,
        const float* __restrict__ W1,
        const float* __restrict__ b1) {
    __shared__ ulonglong2 sW[64 * 16];   // 16 KB
    __shared__ ulonglong2 sb[16];
    int tid = threadIdx.x;
    const ulonglong2* W1v = reinterpret_cast<const ulonglong2*>(W1);
    for (int idx = tid; idx < 64 * 16; idx += 128) sW[idx] = W1v[idx];
    if (tid < 16) sb[tid] = reinterpret_cast<const ulonglong2*>(b1)[tid];
    __syncthreads();

    int n = blockIdx.x * 128 + tid;
    if (n >= N_NODES) return;

    u64 acc[32];
    #pragma unroll
    for (int j = 0; j < 16; j++) { ulonglong2 v = sb[j]; acc[2*j] = v.x; acc[2*j+1] = v.y; }

    const float4* xr = reinterpret_cast<const float4*>(x + (size_t)n * 64);
    #pragma unroll 1
    for (int c = 0; c < 2; c++) {
        float v[32];
        #pragma unroll
        for (int j = 0; j < 8; j++) {
            float4 f = xr[c * 8 + j];
            v[4*j] = f.x; v[4*j+1] = f.y; v[4*j+2] = f.z; v[4*j+3] = f.w;
        }
        #pragma unroll
        for (int i = 0; i < 32; i++) {
            u64 a = pack2(v[i]);
            #pragma unroll
            for (int j = 0; j < 16; j++) {
                ulonglong2 w = sW[(c * 32 + i) * 16 + j];
                ffma2(acc[2*j], a, w.x);
                ffma2(acc[2*j+1], a, w.y);
            }
        }
    }
    ulonglong2* o = reinterpret_cast<ulonglong2*>(g_xw1 + (size_t)n * 64);
    float4* az = reinterpret_cast<float4*>(g_agg + (size_t)n * 64);
    float4 z = make_float4(0.f, 0.f, 0.f, 0.f);
    #pragma unroll
    for (int j = 0; j < 16; j++) {
        ulonglong2 v; v.x = acc[2*j]; v.y = acc[2*j+1]; o[j] = v;
        az[j] = z;
    }
    g_cnt[n] = 0.0f;
}

// ---------------------------------------------------------------------------
// Edge kernel (layer-2 GEMM hoisted out!):
//   h = xw1[src] + ef @ W1[64:80,:] ; scatter relu(h) -> g_agg[dst]; cnt++
// ---------------------------------------------------------------------------
__global__ void __launch_bounds__(256) edge_kernel(
        const int*   __restrict__ ei,
        const float* __restrict__ ef,
        const float* __restrict__ W1) {
    __shared__ ulonglong2 sW1e[16 * 16];  // W1 rows 64..79, 4 KB
    int tid = threadIdx.x;
    const ulonglong2* W1v = reinterpret_cast<const ulonglong2*>(W1);
    for (int idx = tid; idx < 16 * 16; idx += 256) sW1e[idx] = W1v[1024 + idx];
    __syncthreads();

    int e = blockIdx.x * 256 + tid;   // N_EDGES % 256 == 0
    int s = ei[e];
    int d = ei[N_EDGES + e];

    // acc <- xw1[src]  (L2-resident gather)
    u64 acc[32];
    const ulonglong2* xr = reinterpret_cast<const ulonglong2*>(g_xw1 + (size_t)s * 64);
    #pragma unroll
    for (int j = 0; j < 16; j++) { ulonglong2 v = xr[j]; acc[2*j] = v.x; acc[2*j+1] = v.y; }

    float efr[16];
    const float4* er = reinterpret_cast<const float4*>(ef + (size_t)e * 16);
    #pragma unroll
    for (int j = 0; j < 4; j++) {
        float4 f = er[j];
        efr[4*j] = f.x; efr[4*j+1] = f.y; efr[4*j+2] = f.z; efr[4*j+3] = f.w;
    }

    // acc += ef @ W1e
    #pragma unroll
    for (int i = 0; i < 16; i++) {
        u64 a = pack2(efr[i]);
        #pragma unroll
        for (int j = 0; j < 16; j++) {
            ulonglong2 w = sW1e[i * 16 + j];
            ffma2(acc[2*j], a, w.x);
            ffma2(acc[2*j+1], a, w.y);
        }
    }

    // relu + scatter
    float* aggbase = g_agg + (size_t)d * 64;
    #pragma unroll
    for (int j = 0; j < 16; j++) {
        float4 v;
        unpack2(acc[2*j],   v.x, v.y);
        unpack2(acc[2*j+1], v.z, v.w);
        v.x = fmaxf(v.x, 0.f); v.y = fmaxf(v.y, 0.f);
        v.z = fmaxf(v.z, 0.f); v.w = fmaxf(v.w, 0.f);
        red_add_v4(aggbase + 4 * j, v);
    }
    atomicAdd(&g_cnt[d], 1.0f);
}

// ---------------------------------------------------------------------------
// Node stage A: agg_mean = (g_agg[n] @ W2) * inv + b2 * (cnt*inv)  -> g_xw1[n]
// ---------------------------------------------------------------------------
__global__ void __launch_bounds__(128) nodeA_kernel(
        const float* __restrict__ W2,
        const float* __restrict__ b2) {
    __shared__ ulonglong2 sW[64 * 16];   // 16 KB
    __shared__ float sb[64];
    int tid = threadIdx.x;
    const ulonglong2* W2v = reinterpret_cast<const ulonglong2*>(W2);
    for (int idx = tid; idx < 64 * 16; idx += 128) sW[idx] = W2v[idx];
    if (tid < 64) sb[tid] = b2[tid];
    __syncthreads();

    int n = blockIdx.x * 128 + tid;
    if (n >= N_NODES) return;

    float cnt = g_cnt[n];
    float inv = 1.0f / (cnt + 1e-8f);
    float bs  = cnt * inv;

    u64 acc[32];
    #pragma unroll
    for (int j = 0; j < 32; j++) acc[j] = 0ull;

    const float4* ar = reinterpret_cast<const float4*>(g_agg + (size_t)n * 64);
    #pragma unroll 1
    for (int c = 0; c < 2; c++) {
        float v[32];
        #pragma unroll
        for (int j = 0; j < 8; j++) {
            float4 f = ar[c * 8 + j];
            v[4*j] = f.x; v[4*j+1] = f.y; v[4*j+2] = f.z; v[4*j+3] = f.w;
        }
        #pragma unroll
        for (int i = 0; i < 32; i++) {
            u64 a = pack2(v[i]);
            #pragma unroll
            for (int j = 0; j < 16; j++) {
                ulonglong2 w = sW[(c * 32 + i) * 16 + j];
                ffma2(acc[2*j], a, w.x);
                ffma2(acc[2*j+1], a, w.y);
            }
        }
    }
    float4* o = reinterpret_cast<float4*>(g_xw1 + (size_t)n * 64);
    #pragma unroll
    for (int j = 0; j < 16; j++) {
        float4 v;
        unpack2(acc[2*j],   v.x, v.y);
        unpack2(acc[2*j+1], v.z, v.w);
        v.x = v.x * inv + sb[4*j]   * bs;
        v.y = v.y * inv + sb[4*j+1] * bs;
        v.z = v.z * inv + sb[4*j+2] * bs;
        v.w = v.w * inv + sb[4*j+3] * bs;
        o[j] = v;
    }
}

// ---------------------------------------------------------------------------
// Node stage B: y = relu([x, agg_mean] @ W3 + b3) + x ; LayerNorm -> out
// ---------------------------------------------------------------------------
__global__ void __launch_bounds__(128) nodeB_kernel(
        const float* __restrict__ x,
        const float* __restrict__ W3,
        const float* __restrict__ b3,
        const float* __restrict__ gamma,
        const float* __restrict__ beta,
        float* __restrict__ out) {
    __shared__ ulonglong2 sW[128 * 16];  // 32 KB
    __shared__ ulonglong2 sb[16];
    __shared__ float sg[64], sbt[64];
    int tid = threadIdx.x;
    const ulonglong2* W3v = reinterpret_cast<const ulonglong2*>(W3);
    for (int idx = tid; idx < 128 * 16; idx += 128) sW[idx] = W3v[idx];
    if (tid < 16) sb[tid] = reinterpret_cast<const ulonglong2*>(b3)[tid];
    if (tid < 64) { sg[tid] = gamma[tid]; sbt[tid] = beta[tid]; }
    __syncthreads();

    int n = blockIdx.x * 128 + tid;
    if (n >= N_NODES) return;

    u64 acc[32];
    #pragma unroll
    for (int j = 0; j < 16; j++) { ulonglong2 v = sb[j]; acc[2*j] = v.x; acc[2*j+1] = v.y; }

    const float4* xr = reinterpret_cast<const float4*>(x + (size_t)n * 64);
    const float4* ar = reinterpret_cast<const float4*>(g_xw1 + (size_t)n * 64);

    #pragma unroll 1
    for (int c = 0; c < 4; c++) {
        const float4* p = (c < 2) ? (xr + (c & 1) * 8) : (ar + (c & 1) * 8);
        float v[32];
        #pragma unroll
        for (int j = 0; j < 8; j++) {
            float4 f = p[j];
            v[4*j] = f.x; v[4*j+1] = f.y; v[4*j+2] = f.z; v[4*j+3] = f.w;
        }
        #pragma unroll
        for (int i = 0; i < 32; i++) {
            u64 a = pack2(v[i]);
            #pragma unroll
            for (int j = 0; j < 16; j++) {
                ulonglong2 w = sW[(c * 32 + i) * 16 + j];
                ffma2(acc[2*j], a, w.x);
                ffma2(acc[2*j+1], a, w.y);
            }
        }
    }

    // relu + residual
    float u[64];
    #pragma unroll
    for (int j = 0; j < 16; j++) {
        float4 f = xr[j];
        float a0, a1, a2, a3;
        unpack2(acc[2*j],   a0, a1);
        unpack2(acc[2*j+1], a2, a3);
        u[4*j]   = fmaxf(a0, 0.0f) + f.x;
        u[4*j+1] = fmaxf(a1, 0.0f) + f.y;
        u[4*j+2] = fmaxf(a2, 0.0f) + f.z;
        u[4*j+3] = fmaxf(a3, 0.0f) + f.w;
    }

    // LayerNorm (per-thread)
    float s = 0.0f, ss = 0.0f;
    #pragma unroll
    for (int j = 0; j < 64; j++) { s += u[j]; ss = fmaf(u[j], u[j], ss); }
    float mu  = s * (1.0f / 64.0f);
    float var = ss * (1.0f / 64.0f) - mu * mu;
    float r   = rsqrtf(var + 1e-5f);

    float4* o = reinterpret_cast<float4*>(out + (size_t)n * 64);
    #pragma unroll
    for (int j = 0; j < 16; j++) {
        float4 v;
        v.x = (u[4*j]   - mu) * r * sg[4*j]   + sbt[4*j];
        v.y = (u[4*j+1] - mu) * r * sg[4*j+1] + sbt[4*j+1];
        v.z = (u[4*j+2] - mu) * r * sg[4*j+2] + sbt[4*j+2];
        v.w = (u[4*j+3] - mu) * r * sg[4*j+3] + sbt[4*j+3];
        o[j] = v;
    }
}

// ---------------------------------------------------------------------------
extern "C" void kernel_launch(void* const* d_in, const int* in_sizes, int n_in,
                              void* d_out, int out_size) {
    const float* x     = (const float*)d_in[0];
    const int*   ei    = (const int*)  d_in[1];
    const float* ef    = (const float*)d_in[2];
    const float* W1    = (const float*)d_in[3];
    const float* b1    = (const float*)d_in[4];
    const float* W2    = (const float*)d_in[5];
    const float* b2    = (const float*)d_in[6];
    const float* W3    = (const float*)d_in[7];
    const float* b3    = (const float*)d_in[8];
    const float* gamma = (const float*)d_in[9];
    const float* beta  = (const float*)d_in[10];
    float* out = (float*)d_out;

    (void)in_sizes; (void)n_in; (void)out_size;

    precompute_kernel<<<(N_NODES + 127) / 128, 128>>>(x, W1, b1);
    edge_kernel<<<N_EDGES / 256, 256>>>(ei, ef, W1);
    nodeA_kernel<<<(N_NODES + 127) / 128, 128>>>(W2, b2);
    nodeB_kernel<<<(N_NODES + 127) / 128, 128>>>(x, W3, b3, gamma, beta, out);
}